// round 6
// baseline (speedup 1.0000x reference)
#include <cuda_runtime.h>
#include <cstdint>

// ---------------------------------------------------------------------------
// B=64, L=512, Din=256, Dout=256, split=128
// Recurrence: 32 clusters x 4 CTAs. U in registers (f32x2). Single-phase step:
//   wait -> GEMM(mts2[p]) -> shfl-reduce -> eltwise -> scaled DSMEM store into
//   mts2[p^1] of all 4 CTAs -> arrive.  No __syncthreads in the loop.
// ---------------------------------------------------------------------------

#define B_  64
#define L_  512
#define D_  256

__device__ float g_G[(size_t)B_ * L_ * 768];     // ~100.7 MB
__device__ float g_A[(size_t)B_ * L_];           // 128 KB
__device__ float g_hist[(size_t)L_ * B_ * 128];  // hi-half history (thread-private)

// ---------------------------------------------------------------------------
// helpers
// ---------------------------------------------------------------------------
__device__ __forceinline__ unsigned long long ffma2(
    unsigned long long a, unsigned long long b, unsigned long long c)
{
    unsigned long long d;
    asm("fma.rn.f32x2 %0, %1, %2, %3;" : "=l"(d) : "l"(a), "l"(b), "l"(c));
    return d;
}
__device__ __forceinline__ unsigned long long pack2(float x, float y) {
    unsigned long long r;
    asm("mov.b64 %0, {%1, %2};" : "=l"(r) : "f"(x), "f"(y));
    return r;
}
__device__ __forceinline__ void unpack2(unsigned long long v, float& x, float& y) {
    asm("mov.b64 {%0, %1}, %2;" : "=f"(x), "=f"(y) : "l"(v));
}
__device__ __forceinline__ float hadd2(unsigned long long v) {
    float x, y; unpack2(v, x, y); return x + y;
}
__device__ __forceinline__ unsigned smem_u32(const void* p) {
    unsigned a;
    asm("{ .reg .u64 t; cvta.to.shared.u64 t, %1; cvt.u32.u64 %0, t; }" : "=r"(a) : "l"(p));
    return a;
}
__device__ __forceinline__ void mbar_init(unsigned mbar, unsigned cnt) {
    asm volatile("mbarrier.init.shared.b64 [%0], %1;" :: "r"(mbar), "r"(cnt) : "memory");
}
__device__ __forceinline__ void mbar_arrive_remote(unsigned laddr, unsigned rank) {
    asm volatile(
        "{ .reg .b32 ra;\n\t"
        "  mapa.shared::cluster.u32 ra, %0, %1;\n\t"
        "  mbarrier.arrive.release.cluster.shared::cluster.b64 _, [ra]; }"
        :: "r"(laddr), "r"(rank) : "memory");
}
__device__ __forceinline__ void mbar_wait_cta(unsigned mbar, unsigned parity) {
    asm volatile(
        "{\n\t.reg .pred P;\n\t"
        "WL%=:\n\t"
        "mbarrier.try_wait.parity.acquire.cta.shared::cta.b64 P, [%0], %1, 0x989680;\n\t"
        "@!P bra WL%=;\n\t}"
        :: "r"(mbar), "r"(parity) : "memory");
}
__device__ __forceinline__ void dsmem_st(unsigned laddr, unsigned rank, float v) {
    asm volatile(
        "{ .reg .b32 ra; mapa.shared::cluster.u32 ra, %0, %1;"
        "  st.shared::cluster.f32 [ra], %2; }"
        :: "r"(laddr), "r"(rank), "f"(v));
}

// ---------------------------------------------------------------------------
// Kernel 1: G = inp @ Wcat + bias.  128x128x16 fp32 tiles, f32x2 FMA.
// ---------------------------------------------------------------------------
__global__ void __launch_bounds__(256) gemm_pre(
    const float* __restrict__ inp,
    const float* __restrict__ Wr, const float* __restrict__ Wz, const float* __restrict__ Wh,
    const float* __restrict__ br, const float* __restrict__ bz, const float* __restrict__ bh)
{
    __shared__ float As[16][132];
    __shared__ __align__(16) float Bs[16][128];

    const int ntile = blockIdx.x;
    const int mtile = blockIdx.y;
    const int gate  = ntile >> 1;
    const int ncol0 = (ntile & 1) * 128;
    const float* W    = (gate == 0) ? Wr : (gate == 1) ? Wz : Wh;
    const float* bias = (gate == 0) ? br : (gate == 1) ? bz : bh;

    const int tid = threadIdx.x;
    const int tm  = (tid >> 4) * 8;
    const int tn  = (tid & 15) * 8;

    const float* Ag = inp + (size_t)mtile * 128 * D_;
    const float* Bg = W + ncol0;

    const int a_row = tid >> 2;
    const int a_col = (tid & 3) * 4;
    const int b_row = tid >> 5;
    const int b_col = (tid & 31) * 4;

    unsigned long long acc2[8][4];
#pragma unroll
    for (int i = 0; i < 8; ++i)
#pragma unroll
        for (int q = 0; q < 4; ++q) acc2[i][q] = 0ull;

    for (int k0 = 0; k0 < D_; k0 += 16) {
        float4 a0  = *(const float4*)(Ag + (size_t)a_row        * D_ + k0 + a_col);
        float4 a1  = *(const float4*)(Ag + (size_t)(a_row + 64) * D_ + k0 + a_col);
        float4 bv0 = *(const float4*)(Bg + (size_t)(k0 + b_row)     * D_ + b_col);
        float4 bv1 = *(const float4*)(Bg + (size_t)(k0 + b_row + 8) * D_ + b_col);

        __syncthreads();
        As[a_col + 0][a_row] = a0.x; As[a_col + 1][a_row] = a0.y;
        As[a_col + 2][a_row] = a0.z; As[a_col + 3][a_row] = a0.w;
        As[a_col + 0][a_row + 64] = a1.x; As[a_col + 1][a_row + 64] = a1.y;
        As[a_col + 2][a_row + 64] = a1.z; As[a_col + 3][a_row + 64] = a1.w;
        *(float4*)&Bs[b_row][b_col]     = bv0;
        *(float4*)&Bs[b_row + 8][b_col] = bv1;
        __syncthreads();

#pragma unroll
        for (int k = 0; k < 16; ++k) {
            float4 af0 = *(const float4*)&As[k][tm];
            float4 af1 = *(const float4*)&As[k][tm + 4];
            const ulonglong2* bp = (const ulonglong2*)&Bs[k][tn];
            ulonglong2 bA = bp[0], bB = bp[1];
            float am[8] = {af0.x, af0.y, af0.z, af0.w, af1.x, af1.y, af1.z, af1.w};
#pragma unroll
            for (int i = 0; i < 8; ++i) {
                unsigned long long ad = pack2(am[i], am[i]);
                acc2[i][0] = ffma2(ad, bA.x, acc2[i][0]);
                acc2[i][1] = ffma2(ad, bA.y, acc2[i][1]);
                acc2[i][2] = ffma2(ad, bB.x, acc2[i][2]);
                acc2[i][3] = ffma2(ad, bB.y, acc2[i][3]);
            }
        }
    }

    float bb[8];
#pragma unroll
    for (int jj = 0; jj < 8; ++jj) bb[jj] = bias[ncol0 + tn + jj];

    const size_t ng0 = (size_t)gate * 256 + ncol0 + tn;
#pragma unroll
    for (int i = 0; i < 8; ++i) {
        size_t m = (size_t)mtile * 128 + tm + i;
        float o[8];
#pragma unroll
        for (int q = 0; q < 4; ++q) unpack2(acc2[i][q], o[2 * q], o[2 * q + 1]);
#pragma unroll
        for (int jj = 0; jj < 8; ++jj) o[jj] += bb[jj];
        *(float4*)&g_G[m * 768 + ng0]     = make_float4(o[0], o[1], o[2], o[3]);
        *(float4*)&g_G[m * 768 + ng0 + 4] = make_float4(o[4], o[5], o[6], o[7]);
    }
}

// ---------------------------------------------------------------------------
// Kernel 2: a[m] = sigmoid(x[m] . (k1 - k2))
// ---------------------------------------------------------------------------
__global__ void __launch_bounds__(256) avals_kernel(
    const float* __restrict__ inp,
    const float* __restrict__ k1, const float* __restrict__ k2)
{
    const int warp = threadIdx.x >> 5, lane = threadIdx.x & 31;
    const int m = blockIdx.x * 8 + warp;
    const float* x = inp + (size_t)m * D_;
    float s = 0.f;
#pragma unroll
    for (int i = lane; i < D_; i += 32) s += x[i] * (k1[i] - k2[i]);
#pragma unroll
    for (int o = 16; o; o >>= 1) s += __shfl_xor_sync(0xFFFFFFFFu, s, o);
    if (lane == 0) g_A[m] = 1.f / (1.f + __expf(-s));
}

// ---------------------------------------------------------------------------
// Kernel 3: recurrence.
// Thread map: j = (tid>>2)&63 (column dg0+j), kq = tid&3 (k-quarter k0=64*kq).
// Split-K partials reduced with 2 shfl.xor rounds (lanes l, l^1, l^2 share j).
// Lane kq==b runs eltwise for (b, dg0+j) and pushes the PRE-SCALED mt value of
// step t+1 into mts2[p^1] of all 4 CTAs via DSMEM. g_hist is thread-private.
// Per-step sync: one 32-arrival mbarrier per CTA (8 warps x 4 CTAs).
// ---------------------------------------------------------------------------
__global__ void __launch_bounds__(256, 1) __cluster_dims__(4, 1, 1)
recur_kernel(const float* __restrict__ Ur, const float* __restrict__ Uz,
             const float* __restrict__ Uh, const int* __restrict__ ci,
             float* __restrict__ out)
{
    __shared__ __align__(16) float mts2[2 * 2 * 256];   // [phase][b][k]
    __shared__ __align__(16) float a_s[2 * 512];        // [b][t]
    __shared__ __align__(16) int   ci_s[2 * 512];       // [b][t]
    __shared__ __align__(8)  unsigned long long mbar_s;

    const int tid  = threadIdx.x;
    const int rank = blockIdx.x & 3;
    const int grp  = blockIdx.x >> 2;
    const int b0   = grp * 2;
    const int dg0  = rank * 64;

    const int j  = (tid >> 2) & 63;
    const int kq = tid & 3;
    const int k0 = kq * 64;

    const bool act = (kq < 2);        // eltwise-active lane
    const int  b   = kq;              // its batch element (valid when act)
    const int  dg  = dg0 + j;         // its output column
    const bool hi  = (dg >= 128);
    const int  dq  = dg - 128;        // hi-half index (valid when hi)

    // ---- one-time: U slice into registers ----
    unsigned long long u0[32], u1[32], u2[32];
    {
        const float* pr = Ur + (size_t)k0 * D_ + dg0 + j;
        const float* pz = Uz + (size_t)k0 * D_ + dg0 + j;
        const float* ph = Uh + (size_t)k0 * D_ + dg0 + j;
#pragma unroll
        for (int i = 0; i < 32; ++i) {
            u0[i] = pack2(pr[(2 * i) * D_], pr[(2 * i + 1) * D_]);
            u1[i] = pack2(pz[(2 * i) * D_], pz[(2 * i + 1) * D_]);
            u2[i] = pack2(ph[(2 * i) * D_], ph[(2 * i + 1) * D_]);
        }
    }
    {
        const float4* ga = (const float4*)&g_A[(size_t)b0 * L_];
        const int4*   gc = (const int4*)  (ci + (size_t)b0 * L_);
        ((float4*)a_s)[tid] = ga[tid];
        ((int4*)ci_s)[tid]  = gc[tid];
    }
    for (int i = tid; i < 1024; i += 256) mts2[i] = 0.f;   // zero both phases
    if (tid == 0) mbar_init(smem_u32(&mbar_s), 32);
    __syncthreads();
    asm volatile("barrier.cluster.arrive.aligned;" ::: "memory");
    asm volatile("barrier.cluster.wait.aligned;" ::: "memory");

    const unsigned mbar = smem_u32(&mbar_s);

    // pre-loop state (active lanes)
    float gn0 = 0.f, gn1 = 0.f, gn2 = 0.f;
    float vc  = 0.f;                                   // prefetched coref (hi lanes)
    if (act) {
        size_t gb = ((size_t)(b0 + b) * L_) * 768 + dg;
        gn0 = g_G[gb]; gn1 = g_G[gb + 256]; gn2 = g_G[gb + 512];
        // vc for t=0: ci[0] == 0 always -> 0; vc for use at t=0 stays 0.
    }

    for (int t = 0; t < L_; ++t) {
        const int p = t & 1;

        // ---- GEMM: registers x smem-broadcast mts2[p], packed f32x2 ----
        unsigned long long a00 = 0ull, a01 = 0ull;
        unsigned long long a10 = 0ull, a11 = 0ull;
        unsigned long long a20 = 0ull, a21 = 0ull;
        {
            const float* base = &mts2[p * 512];
            const ulonglong2* m0 = (const ulonglong2*)(base + k0);
            const ulonglong2* m1 = (const ulonglong2*)(base + 256 + k0);
#pragma unroll
            for (int i = 0; i < 16; ++i) {
                ulonglong2 v0 = m0[i];
                ulonglong2 v1 = m1[i];
                a00 = ffma2(u0[2 * i], v0.x, a00);
                a01 = ffma2(u0[2 * i], v1.x, a01);
                a10 = ffma2(u1[2 * i], v0.x, a10);
                a11 = ffma2(u1[2 * i], v1.x, a11);
                a20 = ffma2(u2[2 * i], v0.x, a20);
                a21 = ffma2(u2[2 * i], v1.x, a21);
                a00 = ffma2(u0[2 * i + 1], v0.y, a00);
                a01 = ffma2(u0[2 * i + 1], v1.y, a01);
                a10 = ffma2(u1[2 * i + 1], v0.y, a10);
                a11 = ffma2(u1[2 * i + 1], v1.y, a11);
                a20 = ffma2(u2[2 * i + 1], v0.y, a20);
                a21 = ffma2(u2[2 * i + 1], v1.y, a21);
            }
        }
        // ---- split-K reduce across the 4 kq lanes (same j) ----
        float sr0 = hadd2(a00), sr1 = hadd2(a01);
        float sz0 = hadd2(a10), sz1 = hadd2(a11);
        float sh0 = hadd2(a20), sh1 = hadd2(a21);
#pragma unroll
        for (int o = 1; o <= 2; o <<= 1) {
            sr0 += __shfl_xor_sync(0xFFFFFFFFu, sr0, o);
            sr1 += __shfl_xor_sync(0xFFFFFFFFu, sr1, o);
            sz0 += __shfl_xor_sync(0xFFFFFFFFu, sz0, o);
            sz1 += __shfl_xor_sync(0xFFFFFFFFu, sz1, o);
            sh0 += __shfl_xor_sync(0xFFFFFFFFu, sh0, o);
            sh1 += __shfl_xor_sync(0xFFFFFFFFu, sh1, o);
        }

        float h = 0.f;
        const int tn = (t + 1 < L_) ? (t + 1) : (L_ - 1);
        if (act) {
            float Sr = b ? sr1 : sr0;
            float Sz = b ? sz1 : sz0;
            float Sh = b ? sh1 : sh0;
            float r  = 1.f / (1.f + __expf(-(gn0 + Sr)));
            float z  = 1.f / (1.f + __expf(-(gn1 + Sz)));
            float ti = gn2 + r * Sh;
            float th = 2.f / (1.f + __expf(-2.f * ti)) - 1.f;
            float mtd = mts2[p * 512 + b * 256 + dg];
            h = (1.f - z) * mtd + z * th;

            // build step-(t+1) mt value, pre-scaled, and push to all 4 CTAs
            float av = a_s[b * L_ + tn];
            float mtv;
            if (!hi) {
                mtv = av * h;
            } else {
                g_hist[((size_t)t * B_ + b0 + b) * 128 + dq] = h;
                int c1 = ci_s[b * L_ + tn];
                float cv = (c1 - 1 == t) ? h : vc;     // vc==0 covers c1==0
                mtv = (1.f - av) * cv;
            }
            unsigned laddr = smem_u32(&mts2[(p ^ 1) * 512 + b * 256 + dg]);
#pragma unroll
            for (int rr = 0; rr < 4; ++rr) dsmem_st(laddr, rr, mtv);
        }

        __syncwarp();
        if ((tid & 31) < 4) mbar_arrive_remote(mbar, tid & 31);

        // off-critical-path: output, G prefetch, coref prefetch (t+2)
        if (act) {
            out[(((size_t)(b0 + b)) * L_ + t) * D_ + dg] = h;
            size_t gb = ((size_t)(b0 + b) * L_ + tn) * 768 + dg;
            gn0 = g_G[gb]; gn1 = g_G[gb + 256]; gn2 = g_G[gb + 512];
            if (hi) {
                int t2 = (t + 2 < L_) ? (t + 2) : (L_ - 1);
                int c2 = ci_s[b * L_ + t2];
                vc = 0.f;
                if (c2 > 0 && (c2 - 1) <= t)
                    vc = g_hist[((size_t)(c2 - 1) * B_ + b0 + b) * 128 + dq];
                // c2-1 == t+1 handled next step via own h (cflag path)
            }
        }

        mbar_wait_cta(mbar, p);
    }
}

// ---------------------------------------------------------------------------
// launch
// ---------------------------------------------------------------------------
extern "C" void kernel_launch(void* const* d_in, const int* in_sizes, int n_in,
                              void* d_out, int out_size)
{
    const float* inp = (const float*)d_in[0];
    const int*   ci  = (const int*)  d_in[1];
    const float* Wr  = (const float*)d_in[2];
    const float* br  = (const float*)d_in[3];
    const float* Ur  = (const float*)d_in[4];
    const float* Wz  = (const float*)d_in[5];
    const float* bz  = (const float*)d_in[6];
    const float* Uz  = (const float*)d_in[7];
    const float* Wh  = (const float*)d_in[8];
    const float* bh  = (const float*)d_in[9];
    const float* Uh  = (const float*)d_in[10];
    const float* k1  = (const float*)d_in[11];
    const float* k2  = (const float*)d_in[12];
    float* out = (float*)d_out;

    gemm_pre<<<dim3(6, (B_ * L_) / 128), 256>>>(inp, Wr, Wz, Wh, br, bz, bh);
    avals_kernel<<<(B_ * L_) / 8, 256>>>(inp, k1, k2);
    recur_kernel<<<128, 256>>>(Ur, Uz, Uh, ci, out);
}

// round 7
// speedup vs baseline: 1.5339x; 1.5339x over previous
#include <cuda_runtime.h>
#include <cstdint>

// ---------------------------------------------------------------------------
// B=64, L=512, Din=256, Dout=256, split=128
// Recurrence: 32 clusters x 4 CTAs. U in registers (f32x2). Single-phase step:
//   wait -> GEMM(mts2[p]) -> shfl-reduce -> eltwise -> scaled DSMEM store into
//   mts2[p^1] of all 4 CTAs -> arrive.  No __syncthreads in the loop.
// mts2 is PADDED (4 floats per 64-float k-quarter) so the 4 kq lanes hit
// disjoint banks: byte offsets {0,272,544,816} == {0,16,32,48} mod 128.
// ---------------------------------------------------------------------------

#define B_  64
#define L_  512
#define D_  256

// padded mt layout
#define MT_Q    68          // floats per k-quarter (64 + 4 pad)
#define MT_B    272         // floats per b row (4*68)  (272*4 B = 1088 B, 16B-mult)
#define MT_PH   544         // floats per phase (2 b rows)

__device__ float g_G[(size_t)B_ * L_ * 768];     // ~100.7 MB
__device__ float g_A[(size_t)B_ * L_];           // 128 KB
__device__ float g_hist[(size_t)L_ * B_ * 128];  // hi-half history (thread-private)

// ---------------------------------------------------------------------------
// helpers
// ---------------------------------------------------------------------------
__device__ __forceinline__ unsigned long long ffma2(
    unsigned long long a, unsigned long long b, unsigned long long c)
{
    unsigned long long d;
    asm("fma.rn.f32x2 %0, %1, %2, %3;" : "=l"(d) : "l"(a), "l"(b), "l"(c));
    return d;
}
__device__ __forceinline__ unsigned long long pack2(float x, float y) {
    unsigned long long r;
    asm("mov.b64 %0, {%1, %2};" : "=l"(r) : "f"(x), "f"(y));
    return r;
}
__device__ __forceinline__ void unpack2(unsigned long long v, float& x, float& y) {
    asm("mov.b64 {%0, %1}, %2;" : "=f"(x), "=f"(y) : "l"(v));
}
__device__ __forceinline__ float hadd2(unsigned long long v) {
    float x, y; unpack2(v, x, y); return x + y;
}
__device__ __forceinline__ unsigned smem_u32(const void* p) {
    unsigned a;
    asm("{ .reg .u64 t; cvta.to.shared.u64 t, %1; cvt.u32.u64 %0, t; }" : "=r"(a) : "l"(p));
    return a;
}
__device__ __forceinline__ void mbar_init(unsigned mbar, unsigned cnt) {
    asm volatile("mbarrier.init.shared.b64 [%0], %1;" :: "r"(mbar), "r"(cnt) : "memory");
}
__device__ __forceinline__ void mbar_arrive_remote(unsigned laddr, unsigned rank) {
    asm volatile(
        "{ .reg .b32 ra;\n\t"
        "  mapa.shared::cluster.u32 ra, %0, %1;\n\t"
        "  mbarrier.arrive.release.cluster.shared::cluster.b64 _, [ra]; }"
        :: "r"(laddr), "r"(rank) : "memory");
}
__device__ __forceinline__ void mbar_wait_cta(unsigned mbar, unsigned parity) {
    asm volatile(
        "{\n\t.reg .pred P;\n\t"
        "WL%=:\n\t"
        "mbarrier.try_wait.parity.acquire.cta.shared::cta.b64 P, [%0], %1, 0x989680;\n\t"
        "@!P bra WL%=;\n\t}"
        :: "r"(mbar), "r"(parity) : "memory");
}
__device__ __forceinline__ void dsmem_st(unsigned laddr, unsigned rank, float v) {
    asm volatile(
        "{ .reg .b32 ra; mapa.shared::cluster.u32 ra, %0, %1;"
        "  st.shared::cluster.f32 [ra], %2; }"
        :: "r"(laddr), "r"(rank), "f"(v));
}

// ---------------------------------------------------------------------------
// Kernel 1: G = inp @ Wcat + bias.  128x128x16 fp32 tiles, f32x2 FMA.
// ---------------------------------------------------------------------------
__global__ void __launch_bounds__(256) gemm_pre(
    const float* __restrict__ inp,
    const float* __restrict__ Wr, const float* __restrict__ Wz, const float* __restrict__ Wh,
    const float* __restrict__ br, const float* __restrict__ bz, const float* __restrict__ bh)
{
    __shared__ float As[16][132];
    __shared__ __align__(16) float Bs[16][128];

    const int ntile = blockIdx.x;
    const int mtile = blockIdx.y;
    const int gate  = ntile >> 1;
    const int ncol0 = (ntile & 1) * 128;
    const float* W    = (gate == 0) ? Wr : (gate == 1) ? Wz : Wh;
    const float* bias = (gate == 0) ? br : (gate == 1) ? bz : bh;

    const int tid = threadIdx.x;
    const int tm  = (tid >> 4) * 8;
    const int tn  = (tid & 15) * 8;

    const float* Ag = inp + (size_t)mtile * 128 * D_;
    const float* Bg = W + ncol0;

    const int a_row = tid >> 2;
    const int a_col = (tid & 3) * 4;
    const int b_row = tid >> 5;
    const int b_col = (tid & 31) * 4;

    unsigned long long acc2[8][4];
#pragma unroll
    for (int i = 0; i < 8; ++i)
#pragma unroll
        for (int q = 0; q < 4; ++q) acc2[i][q] = 0ull;

    for (int k0 = 0; k0 < D_; k0 += 16) {
        float4 a0  = *(const float4*)(Ag + (size_t)a_row        * D_ + k0 + a_col);
        float4 a1  = *(const float4*)(Ag + (size_t)(a_row + 64) * D_ + k0 + a_col);
        float4 bv0 = *(const float4*)(Bg + (size_t)(k0 + b_row)     * D_ + b_col);
        float4 bv1 = *(const float4*)(Bg + (size_t)(k0 + b_row + 8) * D_ + b_col);

        __syncthreads();
        As[a_col + 0][a_row] = a0.x; As[a_col + 1][a_row] = a0.y;
        As[a_col + 2][a_row] = a0.z; As[a_col + 3][a_row] = a0.w;
        As[a_col + 0][a_row + 64] = a1.x; As[a_col + 1][a_row + 64] = a1.y;
        As[a_col + 2][a_row + 64] = a1.z; As[a_col + 3][a_row + 64] = a1.w;
        *(float4*)&Bs[b_row][b_col]     = bv0;
        *(float4*)&Bs[b_row + 8][b_col] = bv1;
        __syncthreads();

#pragma unroll
        for (int k = 0; k < 16; ++k) {
            float4 af0 = *(const float4*)&As[k][tm];
            float4 af1 = *(const float4*)&As[k][tm + 4];
            const ulonglong2* bp = (const ulonglong2*)&Bs[k][tn];
            ulonglong2 bA = bp[0], bB = bp[1];
            float am[8] = {af0.x, af0.y, af0.z, af0.w, af1.x, af1.y, af1.z, af1.w};
#pragma unroll
            for (int i = 0; i < 8; ++i) {
                unsigned long long ad = pack2(am[i], am[i]);
                acc2[i][0] = ffma2(ad, bA.x, acc2[i][0]);
                acc2[i][1] = ffma2(ad, bA.y, acc2[i][1]);
                acc2[i][2] = ffma2(ad, bB.x, acc2[i][2]);
                acc2[i][3] = ffma2(ad, bB.y, acc2[i][3]);
            }
        }
    }

    float bb[8];
#pragma unroll
    for (int jj = 0; jj < 8; ++jj) bb[jj] = bias[ncol0 + tn + jj];

    const size_t ng0 = (size_t)gate * 256 + ncol0 + tn;
#pragma unroll
    for (int i = 0; i < 8; ++i) {
        size_t m = (size_t)mtile * 128 + tm + i;
        float o[8];
#pragma unroll
        for (int q = 0; q < 4; ++q) unpack2(acc2[i][q], o[2 * q], o[2 * q + 1]);
#pragma unroll
        for (int jj = 0; jj < 8; ++jj) o[jj] += bb[jj];
        *(float4*)&g_G[m * 768 + ng0]     = make_float4(o[0], o[1], o[2], o[3]);
        *(float4*)&g_G[m * 768 + ng0 + 4] = make_float4(o[4], o[5], o[6], o[7]);
    }
}

// ---------------------------------------------------------------------------
// Kernel 2: a[m] = sigmoid(x[m] . (k1 - k2))
// ---------------------------------------------------------------------------
__global__ void __launch_bounds__(256) avals_kernel(
    const float* __restrict__ inp,
    const float* __restrict__ k1, const float* __restrict__ k2)
{
    const int warp = threadIdx.x >> 5, lane = threadIdx.x & 31;
    const int m = blockIdx.x * 8 + warp;
    const float* x = inp + (size_t)m * D_;
    float s = 0.f;
#pragma unroll
    for (int i = lane; i < D_; i += 32) s += x[i] * (k1[i] - k2[i]);
#pragma unroll
    for (int o = 16; o; o >>= 1) s += __shfl_xor_sync(0xFFFFFFFFu, s, o);
    if (lane == 0) g_A[m] = 1.f / (1.f + __expf(-s));
}

// ---------------------------------------------------------------------------
// Kernel 3: recurrence.
// Thread map: j = (tid>>2)&63 (column dg0+j), kq = tid&3 (k-quarter).
// Split-K reduced with 2 shfl.xor. Lane kq==b runs eltwise for (b, dg0+j),
// pushes PRE-SCALED step-(t+1) mt into mts2[p^1] of all 4 CTAs via DSMEM.
// g_hist thread-private. Sync: one 32-arrival mbarrier per CTA per step.
// ---------------------------------------------------------------------------
__global__ void __launch_bounds__(256, 1) __cluster_dims__(4, 1, 1)
recur_kernel(const float* __restrict__ Ur, const float* __restrict__ Uz,
             const float* __restrict__ Uh, const int* __restrict__ ci,
             float* __restrict__ out)
{
    __shared__ __align__(16) float mts2[2 * MT_PH];     // [phase][b][padded k]
    __shared__ __align__(16) float a_s[2 * 512];        // [b][t]
    __shared__ __align__(16) int   ci_s[2 * 512];       // [b][t]
    __shared__ __align__(8)  unsigned long long mbar_s;

    const int tid  = threadIdx.x;
    const int rank = blockIdx.x & 3;
    const int grp  = blockIdx.x >> 2;
    const int b0   = grp * 2;
    const int dg0  = rank * 64;

    const int j  = (tid >> 2) & 63;
    const int kq = tid & 3;
    const int k0 = kq * 64;

    const bool act = (kq < 2);        // eltwise-active lane
    const int  b   = kq;              // its batch element (valid when act)
    const int  dg  = dg0 + j;         // its output column
    const bool hi  = (dg >= 128);
    const int  dq  = dg - 128;        // hi-half index (valid when hi)
    const int  mtoff = dg + 4 * (dg >> 6);   // padded offset of column dg

    // ---- one-time: U slice into registers ----
    unsigned long long u0[32], u1[32], u2[32];
    {
        const float* pr = Ur + (size_t)k0 * D_ + dg0 + j;
        const float* pz = Uz + (size_t)k0 * D_ + dg0 + j;
        const float* ph = Uh + (size_t)k0 * D_ + dg0 + j;
#pragma unroll
        for (int i = 0; i < 32; ++i) {
            u0[i] = pack2(pr[(2 * i) * D_], pr[(2 * i + 1) * D_]);
            u1[i] = pack2(pz[(2 * i) * D_], pz[(2 * i + 1) * D_]);
            u2[i] = pack2(ph[(2 * i) * D_], ph[(2 * i + 1) * D_]);
        }
    }
    {
        const float4* ga = (const float4*)&g_A[(size_t)b0 * L_];
        const int4*   gc = (const int4*)  (ci + (size_t)b0 * L_);
        ((float4*)a_s)[tid] = ga[tid];
        ((int4*)ci_s)[tid]  = gc[tid];
    }
    for (int i = tid; i < 2 * MT_PH; i += 256) mts2[i] = 0.f;
    if (tid == 0) mbar_init(smem_u32(&mbar_s), 32);
    __syncthreads();
    asm volatile("barrier.cluster.arrive.aligned;" ::: "memory");
    asm volatile("barrier.cluster.wait.aligned;" ::: "memory");

    const unsigned mbar = smem_u32(&mbar_s);

    // pre-loop state (active lanes)
    float gn0 = 0.f, gn1 = 0.f, gn2 = 0.f;
    float vc  = 0.f;                                   // prefetched coref (hi lanes)
    if (act) {
        size_t gb = ((size_t)(b0 + b) * L_) * 768 + dg;
        gn0 = g_G[gb]; gn1 = g_G[gb + 256]; gn2 = g_G[gb + 512];
    }

    for (int t = 0; t < L_; ++t) {
        const int p = t & 1;

        // ---- GEMM: registers x smem mts2[p] (conflict-free padded layout) ----
        unsigned long long a00 = 0ull, a01 = 0ull;
        unsigned long long a10 = 0ull, a11 = 0ull;
        unsigned long long a20 = 0ull, a21 = 0ull;
        {
            const float* base = &mts2[p * MT_PH];
            const ulonglong2* m0 = (const ulonglong2*)(base + MT_Q * kq);
            const ulonglong2* m1 = (const ulonglong2*)(base + MT_B + MT_Q * kq);
#pragma unroll
            for (int i = 0; i < 16; ++i) {
                ulonglong2 v0 = m0[i];
                ulonglong2 v1 = m1[i];
                a00 = ffma2(u0[2 * i], v0.x, a00);
                a01 = ffma2(u0[2 * i], v1.x, a01);
                a10 = ffma2(u1[2 * i], v0.x, a10);
                a11 = ffma2(u1[2 * i], v1.x, a11);
                a20 = ffma2(u2[2 * i], v0.x, a20);
                a21 = ffma2(u2[2 * i], v1.x, a21);
                a00 = ffma2(u0[2 * i + 1], v0.y, a00);
                a01 = ffma2(u0[2 * i + 1], v1.y, a01);
                a10 = ffma2(u1[2 * i + 1], v0.y, a10);
                a11 = ffma2(u1[2 * i + 1], v1.y, a11);
                a20 = ffma2(u2[2 * i + 1], v0.y, a20);
                a21 = ffma2(u2[2 * i + 1], v1.y, a21);
            }
        }
        // ---- split-K reduce across the 4 kq lanes (same j) ----
        float sr0 = hadd2(a00), sr1 = hadd2(a01);
        float sz0 = hadd2(a10), sz1 = hadd2(a11);
        float sh0 = hadd2(a20), sh1 = hadd2(a21);
#pragma unroll
        for (int o = 1; o <= 2; o <<= 1) {
            sr0 += __shfl_xor_sync(0xFFFFFFFFu, sr0, o);
            sr1 += __shfl_xor_sync(0xFFFFFFFFu, sr1, o);
            sz0 += __shfl_xor_sync(0xFFFFFFFFu, sz0, o);
            sz1 += __shfl_xor_sync(0xFFFFFFFFu, sz1, o);
            sh0 += __shfl_xor_sync(0xFFFFFFFFu, sh0, o);
            sh1 += __shfl_xor_sync(0xFFFFFFFFu, sh1, o);
        }

        float h = 0.f;
        const int tn = (t + 1 < L_) ? (t + 1) : (L_ - 1);
        if (act) {
            float Sr = b ? sr1 : sr0;
            float Sz = b ? sz1 : sz0;
            float Sh = b ? sh1 : sh0;
            float r  = 1.f / (1.f + __expf(-(gn0 + Sr)));
            float z  = 1.f / (1.f + __expf(-(gn1 + Sz)));
            float ti = gn2 + r * Sh;
            float th = 2.f / (1.f + __expf(-2.f * ti)) - 1.f;
            float mtd = mts2[p * MT_PH + b * MT_B + mtoff];
            h = (1.f - z) * mtd + z * th;

            // build step-(t+1) mt value, pre-scaled, and push to all 4 CTAs
            float av = a_s[b * L_ + tn];
            float mtv;
            if (!hi) {
                mtv = av * h;
            } else {
                g_hist[((size_t)t * B_ + b0 + b) * 128 + dq] = h;
                int c1 = ci_s[b * L_ + tn];
                float cv = (c1 - 1 == t) ? h : vc;     // vc==0 covers c1==0
                mtv = (1.f - av) * cv;
            }
            unsigned laddr = smem_u32(&mts2[(p ^ 1) * MT_PH + b * MT_B + mtoff]);
#pragma unroll
            for (int rr = 0; rr < 4; ++rr) dsmem_st(laddr, rr, mtv);
        }

        __syncwarp();
        if ((tid & 31) < 4) mbar_arrive_remote(mbar, tid & 31);

        // off-critical-path: output, G prefetch, coref prefetch (t+2)
        if (act) {
            out[(((size_t)(b0 + b)) * L_ + t) * D_ + dg] = h;
            size_t gb = ((size_t)(b0 + b) * L_ + tn) * 768 + dg;
            gn0 = g_G[gb]; gn1 = g_G[gb + 256]; gn2 = g_G[gb + 512];
            if (hi) {
                int t2 = (t + 2 < L_) ? (t + 2) : (L_ - 1);
                int c2 = ci_s[b * L_ + t2];
                vc = 0.f;
                if (c2 > 0 && (c2 - 1) <= t)
                    vc = g_hist[((size_t)(c2 - 1) * B_ + b0 + b) * 128 + dq];
                // c2-1 == t+1 handled next step via own h
            }
        }

        mbar_wait_cta(mbar, p);
    }
}

// ---------------------------------------------------------------------------
// launch
// ---------------------------------------------------------------------------
extern "C" void kernel_launch(void* const* d_in, const int* in_sizes, int n_in,
                              void* d_out, int out_size)
{
    const float* inp = (const float*)d_in[0];
    const int*   ci  = (const int*)  d_in[1];
    const float* Wr  = (const float*)d_in[2];
    const float* br  = (const float*)d_in[3];
    const float* Ur  = (const float*)d_in[4];
    const float* Wz  = (const float*)d_in[5];
    const float* bz  = (const float*)d_in[6];
    const float* Uz  = (const float*)d_in[7];
    const float* Wh  = (const float*)d_in[8];
    const float* bh  = (const float*)d_in[9];
    const float* Uh  = (const float*)d_in[10];
    const float* k1  = (const float*)d_in[11];
    const float* k2  = (const float*)d_in[12];
    float* out = (float*)d_out;

    gemm_pre<<<dim3(6, (B_ * L_) / 128), 256>>>(inp, Wr, Wz, Wh, br, bz, bh);
    avals_kernel<<<(B_ * L_) / 8, 256>>>(inp, k1, k2);
    recur_kernel<<<128, 256>>>(Ur, Uz, Uh, ci, out);
}